// round 1
// baseline (speedup 1.0000x reference)
#include <cuda_runtime.h>
#include <cstdint>

// TaylorMap: out = x + poly3(x) @ W
//   x : [262144, 16] f32,  W : [969, 16] f32,  out : [262144, 16] f32
// Feature ordering (matches reference _poly):
//   row 0          : 1
//   rows 1..16     : x_i
//   rows 17..152   : x_a * x_b   (a = 0..15, b = 0..a)  -> 17 + a(a+1)/2 + b
//   rows 153..968  : x_i*x_a*x_b (i >= a >= b)          -> 153 + C(i+2,3) + a(a+1)/2 + b

#define NF 16
#define BASE2 17
#define BASE3 153
#define N3 816
#define BLOCK 256
#define ROWS_PER_CTA 512          // 2 rows per thread
#define NBATCH 262144

typedef unsigned long long u64;

// ---- f32x2 packed helpers (FFMA2 path: only reachable via PTX) ----
__device__ __forceinline__ u64 pk2(float lo, float hi) {
    u64 r; asm("mov.b64 %0, {%1, %2};" : "=l"(r) : "f"(lo), "f"(hi)); return r;
}
__device__ __forceinline__ void upk2(u64 v, float& lo, float& hi) {
    asm("mov.b64 {%0, %1}, %2;" : "=f"(lo), "=f"(hi) : "l"(v));
}
__device__ __forceinline__ u64 f2fma(u64 a, u64 b, u64 c) {
    u64 d; asm("fma.rn.f32x2 %0, %1, %2, %3;" : "=l"(d) : "l"(a), "l"(b), "l"(c)); return d;
}
__device__ __forceinline__ u64 f2mul(u64 a, u64 b) {
    u64 d; asm("mul.rn.f32x2 %0, %1, %2;" : "=l"(d) : "l"(a), "l"(b)); return d;
}
__device__ __forceinline__ u64 f2add(u64 a, u64 b) {
    u64 d; asm("add.rn.f32x2 %0, %1, %2;" : "=l"(d) : "l"(a), "l"(b)); return d;
}

// smem: [0, 153*16 floats)   scalar W rows for deg 0..2      (9,792 B)
//       [9792, +816*16 u64)  pair-duplicated W rows for deg3 (104,448 B)
#define SMEM_BYTES (BASE3 * NF * 4 + N3 * NF * 8)

__global__ void __launch_bounds__(BLOCK, 2)
taylor_kernel(const float* __restrict__ x, const float* __restrict__ W,
              float* __restrict__ out)
{
    extern __shared__ unsigned char smem_raw[];
    float* sW012 = reinterpret_cast<float*>(smem_raw);
    u64*   sW3   = reinterpret_cast<u64*>(smem_raw + BASE3 * NF * 4);

    const int tid = threadIdx.x;

    // cooperative W load
    #pragma unroll 1
    for (int e = tid; e < BASE3 * NF; e += BLOCK) sW012[e] = W[e];
    #pragma unroll 1
    for (int e = tid; e < N3 * NF; e += BLOCK) {
        float w = W[BASE3 * NF + e];
        sW3[e] = pk2(w, w);
    }
    __syncthreads();

    const long long r0 = (long long)blockIdx.x * ROWS_PER_CTA + tid;
    const long long r1 = r0 + BLOCK;

    const float4* xa = reinterpret_cast<const float4*>(x + r0 * NF);
    const float4* xb = reinterpret_cast<const float4*>(x + r1 * NF);

    u64 X[NF];
    #pragma unroll
    for (int q = 0; q < 4; q++) {
        float4 va = xa[q], vb = xb[q];
        X[q * 4 + 0] = pk2(va.x, vb.x);
        X[q * 4 + 1] = pk2(va.y, vb.y);
        X[q * 4 + 2] = pk2(va.z, vb.z);
        X[q * 4 + 3] = pk2(va.w, vb.w);
    }

    u64 acc[NF];
    // residual + constant term: acc_j = x_j + W[0][j]
    #pragma unroll
    for (int j = 0; j < NF; j++) {
        float w = sW012[j];
        acc[j] = f2add(X[j], pk2(w, w));
    }

    // degree 1
    #pragma unroll
    for (int i = 0; i < NF; i++) {
        const float* wr = &sW012[(1 + i) * NF];
        #pragma unroll
        for (int j = 0; j < NF; j++) {
            float w = wr[j];
            acc[j] = f2fma(X[i], pk2(w, w), acc[j]);
        }
    }

    // degree 2 & 3 fused: p = x_a*x_b is the deg2 monomial (a>=b);
    // q = x_i*p for i>=a covers all deg3 monomials (i>=a>=b).
    #pragma unroll
    for (int ia = 0; ia < NF; ia++) {
        #pragma unroll
        for (int ib = 0; ib <= ia; ib++) {
            u64 p = f2mul(X[ia], X[ib]);
            const float* wr2 = &sW012[(BASE2 + (ia * (ia + 1)) / 2 + ib) * NF];
            #pragma unroll
            for (int j = 0; j < NF; j++) {
                float w = wr2[j];
                acc[j] = f2fma(p, pk2(w, w), acc[j]);
            }
            #pragma unroll
            for (int ii = ia; ii < NF; ii++) {
                u64 qm = f2mul(X[ii], p);
                const int row3 = (ii * (ii + 1) * (ii + 2)) / 6
                               + (ia * (ia + 1)) / 2 + ib;
                const ulonglong2* wv =
                    reinterpret_cast<const ulonglong2*>(&sW3[row3 * NF]);
                #pragma unroll
                for (int j = 0; j < 8; j++) {
                    ulonglong2 wp = wv[j];
                    acc[2 * j + 0] = f2fma(qm, wp.x, acc[2 * j + 0]);
                    acc[2 * j + 1] = f2fma(qm, wp.y, acc[2 * j + 1]);
                }
            }
        }
    }

    // store both rows
    float4* oa = reinterpret_cast<float4*>(out + r0 * NF);
    float4* ob = reinterpret_cast<float4*>(out + r1 * NF);
    #pragma unroll
    for (int q = 0; q < 4; q++) {
        float4 va, vb;
        upk2(acc[q * 4 + 0], va.x, vb.x);
        upk2(acc[q * 4 + 1], va.y, vb.y);
        upk2(acc[q * 4 + 2], va.z, vb.z);
        upk2(acc[q * 4 + 3], va.w, vb.w);
        oa[q] = va;
        ob[q] = vb;
    }
}

extern "C" void kernel_launch(void* const* d_in, const int* in_sizes, int n_in,
                              void* d_out, int out_size)
{
    const float* x = (const float*)d_in[0];   // [262144, 16]
    const float* W = (const float*)d_in[1];   // [969, 16]
    float* out = (float*)d_out;

    cudaFuncSetAttribute(taylor_kernel,
                         cudaFuncAttributeMaxDynamicSharedMemorySize,
                         SMEM_BYTES);

    const int grid = NBATCH / ROWS_PER_CTA;   // 512 CTAs
    taylor_kernel<<<grid, BLOCK, SMEM_BYTES>>>(x, W, out);
}

// round 2
// speedup vs baseline: 1.4902x; 1.4902x over previous
#include <cuda_runtime.h>
#include <cstdint>

// TaylorMap: out = x + poly3(x) @ W
//   x : [262144, 16] f32,  W : [969, 16] f32,  out : [262144, 16] f32
//
// Feature ordering (matches reference _poly):
//   row 0          : 1
//   rows 1..16     : x_i                       (identity residual FOLDED in here)
//   rows 17..152   : x_a * x_b   (a>=b)        -> 17 + a(a+1)/2 + b
//   rows 153..968  : x_i*x_a*x_b (i>=a>=b)     -> 153 + C(i+2,3) + a(a+1)/2 + b
//
// Layout: each thread computes a 4-row x 8-col output tile.
//   f32x2 packing axis = OUTPUT COLUMNS (2 adjacent cols per u64), so W is read
//   as plain contiguous u64 from scalar smem (no duplication -> 4x less LDS).
//   Monomials are computed row-pair-packed (f2mul) and redistributed with
//   cheap dup movs (ALU pipe).

#define NF 16
#define NPOLY 969
#define BLOCK 256
#define NBATCH 262144

typedef unsigned long long u64;

__device__ __forceinline__ u64 pk2(float lo, float hi) {
    u64 r; asm("mov.b64 %0, {%1, %2};" : "=l"(r) : "f"(lo), "f"(hi)); return r;
}
__device__ __forceinline__ void upk2(u64 v, float& lo, float& hi) {
    asm("mov.b64 {%0, %1}, %2;" : "=f"(lo), "=f"(hi) : "l"(v));
}
__device__ __forceinline__ float lo2(u64 v) { float a, b; upk2(v, a, b); return a; }
__device__ __forceinline__ float hi2(u64 v) { float a, b; upk2(v, a, b); return b; }
__device__ __forceinline__ u64 dup_lo(u64 v) { float a = lo2(v); return pk2(a, a); }
__device__ __forceinline__ u64 dup_hi(u64 v) { float a = hi2(v); return pk2(a, a); }

__device__ __forceinline__ u64 f2fma(u64 a, u64 b, u64 c) {
    u64 d; asm("fma.rn.f32x2 %0, %1, %2, %3;" : "=l"(d) : "l"(a), "l"(b), "l"(c)); return d;
}
__device__ __forceinline__ u64 f2mul(u64 a, u64 b) {
    u64 d; asm("mul.rn.f32x2 %0, %1, %2;" : "=l"(d) : "l"(a), "l"(b)); return d;
}

#define SMEM_BYTES (NPOLY * NF * 4)   // 62,016 B scalar W (identity folded)

__global__ void __launch_bounds__(BLOCK, 2)
taylor_kernel(const float* __restrict__ x, const float* __restrict__ W,
              float* __restrict__ out)
{
    extern __shared__ unsigned char smem_raw[];
    float* sW = reinterpret_cast<float*>(smem_raw);

    const int tid = threadIdx.x;

    // Cooperative W load; fold identity residual into deg-1 rows:
    // out = x + poly@W  ==  poly@W'  with  W'[1+i][i] = W[1+i][i] + 1.
    #pragma unroll 1
    for (int e = tid; e < NPOLY * NF; e += BLOCK) {
        float w = W[e];
        int row = e >> 4, col = e & 15;
        if (row - 1 == col) w += 1.0f;
        sW[e] = w;
    }
    __syncthreads();

    const int gtid = blockIdx.x * BLOCK + tid;
    const int cg = gtid & 1;                      // column half: cols [8cg, 8cg+8)
    const long long rbase = (long long)(gtid >> 1) * 4;   // 4 batch rows

    // W access base for this thread: u64 view, row stride = 8 u64, offset cg*4
    const char* wrow_base = reinterpret_cast<const char*>(sW) + cg * 32;

    // ---- load 4 rows of x, pack as row-pairs (for monomial f2mul) ----
    const float4* xv = reinterpret_cast<const float4*>(x + rbase * NF);
    u64 xx01[NF], xx23[NF];
    #pragma unroll
    for (int q = 0; q < 4; q++) {
        float4 a = xv[q];          // row 0
        float4 b = xv[4 + q];      // row 1
        float4 c = xv[8 + q];      // row 2
        float4 d = xv[12 + q];     // row 3
        xx01[q * 4 + 0] = pk2(a.x, b.x);  xx23[q * 4 + 0] = pk2(c.x, d.x);
        xx01[q * 4 + 1] = pk2(a.y, b.y);  xx23[q * 4 + 1] = pk2(c.y, d.y);
        xx01[q * 4 + 2] = pk2(a.z, b.z);  xx23[q * 4 + 2] = pk2(c.z, d.z);
        xx01[q * 4 + 3] = pk2(a.w, b.w);  xx23[q * 4 + 3] = pk2(c.w, d.w);
    }

    // ---- acc[r*4 + c] holds output cols (8cg+2c, 8cg+2c+1) of row r ----
    u64 acc[16];
    {   // degree-0: acc = W'[0][cols]  (same for all 4 rows)
        const ulonglong2* wp = reinterpret_cast<const ulonglong2*>(wrow_base);
        ulonglong2 w0 = wp[0], w1 = wp[1];
        #pragma unroll
        for (int r = 0; r < 4; r++) {
            acc[r * 4 + 0] = w0.x; acc[r * 4 + 1] = w0.y;
            acc[r * 4 + 2] = w1.x; acc[r * 4 + 3] = w1.y;
        }
    }

    // Apply one feature row: monomial values m01 (rows 0,1 packed), m23 (rows 2,3)
    #define APPLY(ridx, m01, m23) do {                                          \
        u64 d0 = dup_lo(m01), d1 = dup_hi(m01);                                 \
        u64 d2 = dup_lo(m23), d3 = dup_hi(m23);                                 \
        const ulonglong2* wp =                                                  \
            reinterpret_cast<const ulonglong2*>(wrow_base + (ridx) * 64);       \
        ulonglong2 w0 = wp[0], w1 = wp[1];                                      \
        acc[0]  = f2fma(d0, w0.x, acc[0]);  acc[1]  = f2fma(d0, w0.y, acc[1]);  \
        acc[2]  = f2fma(d0, w1.x, acc[2]);  acc[3]  = f2fma(d0, w1.y, acc[3]);  \
        acc[4]  = f2fma(d1, w0.x, acc[4]);  acc[5]  = f2fma(d1, w0.y, acc[5]);  \
        acc[6]  = f2fma(d1, w1.x, acc[6]);  acc[7]  = f2fma(d1, w1.y, acc[7]);  \
        acc[8]  = f2fma(d2, w0.x, acc[8]);  acc[9]  = f2fma(d2, w0.y, acc[9]);  \
        acc[10] = f2fma(d2, w1.x, acc[10]); acc[11] = f2fma(d2, w1.y, acc[11]); \
        acc[12] = f2fma(d3, w0.x, acc[12]); acc[13] = f2fma(d3, w0.y, acc[13]); \
        acc[14] = f2fma(d3, w1.x, acc[14]); acc[15] = f2fma(d3, w1.y, acc[15]); \
    } while (0)

    // degree 1 (identity already folded into W')
    #pragma unroll
    for (int i = 0; i < NF; i++) {
        APPLY(1 + i, xx01[i], xx23[i]);
    }

    // degree 2 & 3 fused
    #pragma unroll
    for (int ia = 0; ia < NF; ia++) {
        #pragma unroll
        for (int ib = 0; ib <= ia; ib++) {
            u64 p01 = f2mul(xx01[ia], xx01[ib]);
            u64 p23 = f2mul(xx23[ia], xx23[ib]);
            APPLY(17 + (ia * (ia + 1)) / 2 + ib, p01, p23);
            #pragma unroll
            for (int ii = ia; ii < NF; ii++) {
                u64 q01 = f2mul(xx01[ii], p01);
                u64 q23 = f2mul(xx23[ii], p23);
                const int row3 = 153 + (ii * (ii + 1) * (ii + 2)) / 6
                               + (ia * (ia + 1)) / 2 + ib;
                APPLY(row3, q01, q23);
            }
        }
    }
    #undef APPLY

    // ---- store: acc u64 pairs are directly contiguous output columns ----
    #pragma unroll
    for (int r = 0; r < 4; r++) {
        ulonglong2 s0; s0.x = acc[r * 4 + 0]; s0.y = acc[r * 4 + 1];
        ulonglong2 s1; s1.x = acc[r * 4 + 2]; s1.y = acc[r * 4 + 3];
        ulonglong2* op = reinterpret_cast<ulonglong2*>(out + (rbase + r) * NF + 8 * cg);
        op[0] = s0;
        op[1] = s1;
    }
}

extern "C" void kernel_launch(void* const* d_in, const int* in_sizes, int n_in,
                              void* d_out, int out_size)
{
    const float* x = (const float*)d_in[0];   // [262144, 16]
    const float* W = (const float*)d_in[1];   // [969, 16]
    float* out = (float*)d_out;

    cudaFuncSetAttribute(taylor_kernel,
                         cudaFuncAttributeMaxDynamicSharedMemorySize,
                         SMEM_BYTES);

    // 131072 threads: each does 4 rows x 8 cols
    const int grid = (NBATCH / 4) * 2 / BLOCK;   // 512 CTAs
    taylor_kernel<<<grid, BLOCK, SMEM_BYTES>>>(x, W, out);
}